// round 9
// baseline (speedup 1.0000x reference)
#include <cuda_runtime.h>
#include <cuda_bf16.h>
#include <cstdint>

// Problem dims (fixed by reference)
#define BB 8
#define TT 2048
#define CC 1024
#define DD 64
#define ROWS (BB*TT)      // 16384
#define S_SPLIT 4
#define NEG_BIG  (-1.0e30f)
#define MASK_S   (-3.0e38f)

#define NTOT 192          // fused proj cols: 64 K | 64 Q | 64 V
#define KC 32
#define NCHUNK (CC/KC)    // 32

// proj smem (bf16, padded rows: 40 elems = 80B stride)
#define XPITCH 80
#define WPITCH 80
#define XH_BYTES (128*XPITCH)
#define WH_BYTES (NTOT*WPITCH)
#define STAGE_BYTES (2*XH_BYTES + 2*WH_BYTES)
#define SMEM_PROJ (2*STAGE_BYTES)

// attn smem: bf16 pitch 72 elems = 144B (odd 16B multiple -> conflict-free LDSM)
#define QBLK 256
#define APITCH 144
#define Q_BYTES (QBLK*APITCH)       // 36864 per array
#define KV_ARR  (64*APITCH)         // 9216 per array
#define KV_STAGE (4*KV_ARR)         // 36864 (Khi,Klo,Vhi,Vlo)
#define SMEM_ATT (2*Q_BYTES + 2*KV_STAGE)   // 147456

// Scratch (allocation-free: __device__ globals)
__device__ float g_po[S_SPLIT*ROWS*DD];
__device__ float g_pml[ROWS*8];       // [row][0..3]=m per split, [4..7]=l
__device__ __nv_bfloat16 g_wthi[NTOT*CC];
__device__ __nv_bfloat16 g_wtlo[NTOT*CC];
__device__ __nv_bfloat16 g_qhi[ROWS*DD], g_qlo[ROWS*DD];
__device__ __nv_bfloat16 g_khi[ROWS*DD], g_klo[ROWS*DD];
__device__ __nv_bfloat16 g_vhi[ROWS*DD], g_vlo[ROWS*DD];

__device__ __forceinline__ void cpasync16u(uint32_t sa, const void* g){
  asm volatile("cp.async.cg.shared.global [%0], [%1], 16;\n" :: "r"(sa), "l"(g) : "memory");
}
__device__ __forceinline__ void cp_commit(){ asm volatile("cp.async.commit_group;\n" ::: "memory"); }
__device__ __forceinline__ void cp_wait0(){ asm volatile("cp.async.wait_group 0;\n" ::: "memory"); }
__device__ __forceinline__ void cp_wait1(){ asm volatile("cp.async.wait_group 1;\n" ::: "memory"); }

__device__ __forceinline__ uint32_t smem_u32(const void* p){
  return (uint32_t)__cvta_generic_to_shared(p);
}
__device__ __forceinline__ void ldm4(uint32_t* r, uint32_t addr){
  asm volatile("ldmatrix.sync.aligned.m8n8.x4.shared.b16 {%0,%1,%2,%3},[%4];"
    : "=r"(r[0]), "=r"(r[1]), "=r"(r[2]), "=r"(r[3]) : "r"(addr));
}
__device__ __forceinline__ void ldm4t(uint32_t* r, uint32_t addr){
  asm volatile("ldmatrix.sync.aligned.m8n8.x4.trans.shared.b16 {%0,%1,%2,%3},[%4];"
    : "=r"(r[0]), "=r"(r[1]), "=r"(r[2]), "=r"(r[3]) : "r"(addr));
}
__device__ __forceinline__ void mma16816(float* d, const uint32_t* a,
                                         uint32_t b0, uint32_t b1){
  asm volatile("mma.sync.aligned.m16n8k16.row.col.f32.bf16.bf16.f32 "
    "{%0,%1,%2,%3},{%4,%5,%6,%7},{%8,%9},{%0,%1,%2,%3};"
    : "+f"(d[0]), "+f"(d[1]), "+f"(d[2]), "+f"(d[3])
    : "r"(a[0]), "r"(a[1]), "r"(a[2]), "r"(a[3]), "r"(b0), "r"(b1));
}
// pack (a -> low half, b -> high half) with exact fp32 residual in lo
__device__ __forceinline__ void bf16split2(float a, float b, uint32_t &hi, uint32_t &lo){
  asm("cvt.rn.bf16x2.f32 %0, %1, %2;" : "=r"(hi) : "f"(b), "f"(a));
  float fa = __uint_as_float(hi << 16);
  float fb = __uint_as_float(hi & 0xffff0000u);
  asm("cvt.rn.bf16x2.f32 %0, %1, %2;" : "=r"(lo) : "f"(b - fb), "f"(a - fa));
}

// ---------------------------------------------------------------------------
// Kernel 0: split W into bf16 hi/lo, transposed [n][k].
// ---------------------------------------------------------------------------
__global__ __launch_bounds__(256) void prep_w(
    const float* __restrict__ Wk, const float* __restrict__ Wq,
    const float* __restrict__ Wv)
{
  int n = blockIdx.x;
  const float* W = (n < 64) ? Wk : ((n < 128) ? Wq : Wv);
  int col = n & 63;
  for (int k = threadIdx.x; k < CC; k += 256) {
    float w = W[(size_t)k * DD + col];
    __nv_bfloat16 h = __float2bfloat16(w);
    __nv_bfloat16 l = __float2bfloat16(w - __bfloat162float(h));
    g_wthi[n * CC + k] = h;
    g_wtlo[n * CC + k] = l;
  }
}

// ---------------------------------------------------------------------------
// Kernel 1: QKV projection via mma.sync (3-term split). 512 threads,
// 16 warps, warp tile 16x96 -> 4 warps/SMSP. Epilogue writes bf16 hi/lo
// Q(pre-scaled 0.125)/K/V.
// ---------------------------------------------------------------------------
extern __shared__ char dsmem[];

__global__ __launch_bounds__(512) void proj_mma(const float* __restrict__ x)
{
  const int tid  = threadIdx.x;
  const int wid  = tid >> 5;
  const int lane = tid & 31;
  const int rowBase = blockIdx.x * 128;

  const uint32_t sbase = smem_u32(dsmem);
  auto xhiB = [&](int st){ return sbase + (uint32_t)st * STAGE_BYTES; };
  auto xloB = [&](int st){ return xhiB(st) + XH_BYTES; };
  auto whiB = [&](int st){ return xhiB(st) + 2 * XH_BYTES; };
  auto wloB = [&](int st){ return whiB(st) + WH_BYTES; };

  const int wm = (wid & 7) * 16;       // 8 row groups x 16
  const int wn = (wid >> 3) * 96;      // 2 col groups x 96

  const uint32_t aOff = (uint32_t)((wm + (lane & 15)) * XPITCH + (lane >> 4) * 16);
  const int bN = wn + ((lane >> 4) & 1) * 8 + (lane & 7);
  const uint32_t bOff = (uint32_t)(bN * WPITCH + ((lane >> 3) & 1) * 16);

  float d[12][4];
  #pragma unroll
  for (int nf = 0; nf < 12; nf++)
    #pragma unroll
    for (int c = 0; c < 4; c++) d[nf][c] = 0.f;

  float4 xr[2];
  auto loadX = [&](int chunk) {
    const int k0 = chunk * KC;
    #pragma unroll
    for (int i = 0; i < 2; i++) {
      int f = i * 512 + tid;            // 0..1023 float4 units
      int row = f >> 3, kc = (f & 7) * 4;
      xr[i] = *(const float4*)(x + (size_t)(rowBase + row) * CC + k0 + kc);
    }
  };
  auto convertX = [&](int st) {
    const uint32_t xh = xhiB(st), xl = xloB(st);
    #pragma unroll
    for (int i = 0; i < 2; i++) {
      int f = i * 512 + tid;
      int row = f >> 3;
      uint32_t boff = (uint32_t)(row * XPITCH + (f & 7) * 8);
      float4 v = xr[i];
      uint32_t h01, h23, l01, l23;
      bf16split2(v.x, v.y, h01, l01);
      bf16split2(v.z, v.w, h23, l23);
      asm volatile("st.shared.v2.b32 [%0], {%1,%2};" :: "r"(xh + boff), "r"(h01), "r"(h23) : "memory");
      asm volatile("st.shared.v2.b32 [%0], {%1,%2};" :: "r"(xl + boff), "r"(l01), "r"(l23) : "memory");
    }
  };
  auto issueW = [&](int chunk, int st) {
    const int k0 = chunk * KC;
    const uint32_t wh = whiB(st), wl = wloB(st);
    #pragma unroll
    for (int i = 0; i < 3; i++) {
      int gid = i * 512 + tid;             // 0..1535
      int half = (gid >= 768) ? 1 : 0;
      int g2 = gid - half * 768;
      int n = g2 >> 2, c = g2 & 3;
      const __nv_bfloat16* src =
          (half ? g_wtlo : g_wthi) + (size_t)n * CC + k0 + c * 8;
      uint32_t dst = (half ? wl : wh) + (uint32_t)(n * WPITCH + c * 16);
      cpasync16u(dst, src);
    }
    cp_commit();
  };

  loadX(0);
  issueW(0, 0);
  convertX(0);
  loadX(1);

  for (int it = 0; it < NCHUNK; it++) {
    const int cur = it & 1;
    cp_wait0();
    __syncthreads();
    if (it + 1 < NCHUNK) issueW(it + 1, cur ^ 1);

    #pragma unroll
    for (int ks = 0; ks < 2; ks++) {
      uint32_t ahi[4], alo[4];
      ldm4(ahi, xhiB(cur) + aOff + (uint32_t)(ks * 32));
      ldm4(alo, xloB(cur) + aOff + (uint32_t)(ks * 32));
      #pragma unroll
      for (int nf2 = 0; nf2 < 6; nf2++) {
        uint32_t bhi[4], blo[4];
        uint32_t off = bOff + (uint32_t)(nf2 * 16 * WPITCH + ks * 32);
        ldm4(bhi, whiB(cur) + off);
        ldm4(blo, wloB(cur) + off);
        #pragma unroll
        for (int s = 0; s < 2; s++) {
          float* dd = d[2 * nf2 + s];
          mma16816(dd, ahi, bhi[2 * s], bhi[2 * s + 1]);
          mma16816(dd, ahi, blo[2 * s], blo[2 * s + 1]);
          mma16816(dd, alo, bhi[2 * s], bhi[2 * s + 1]);
        }
      }
    }

    if (it + 1 < NCHUNK) convertX(cur ^ 1);
    if (it + 2 < NCHUNK) loadX(it + 2);
  }

  // epilogue: split fp32 results to bf16 hi/lo gmem (Q scaled by 0.125)
  const int erow = lane >> 2;
  const int ecol = (lane & 3) * 2;
  #pragma unroll
  for (int nf = 0; nf < 12; nf++) {
    int n0 = wn + nf * 8;
    int part = n0 >> 6;
    __nv_bfloat16* hp = (part == 0) ? g_khi : ((part == 1) ? g_qhi : g_vhi);
    __nv_bfloat16* lp = (part == 0) ? g_klo : ((part == 1) ? g_qlo : g_vlo);
    float sc = (part == 1) ? 0.125f : 1.0f;
    int col = (n0 & 63) + ecol;
    size_t r0 = (size_t)(rowBase + wm + erow);
    uint32_t h, l2;
    bf16split2(d[nf][0] * sc, d[nf][1] * sc, h, l2);
    *(uint32_t*)(hp + r0 * DD + col) = h;
    *(uint32_t*)(lp + r0 * DD + col) = l2;
    bf16split2(d[nf][2] * sc, d[nf][3] * sc, h, l2);
    *(uint32_t*)(hp + (r0 + 8) * DD + col) = h;
    *(uint32_t*)(lp + (r0 + 8) * DD + col) = l2;
  }
}

// ---------------------------------------------------------------------------
// Kernel 2: FlashAttention-2 on mma.sync. 512 threads (16 warps, m16 each),
// 256-query blocks. grid=(TT/QBLK, BB, 4), heavy-first qb order. Strided
// split-KV (tile j -> split j%4), per-warp skip of fully-masked tiles.
// ---------------------------------------------------------------------------
__global__ __launch_bounds__(512) void attn_mma()
{
  const int qb  = (TT / QBLK - 1) - blockIdx.x;   // heavy-first
  const int b   = blockIdx.y;
  const int sp  = blockIdx.z;
  const int tid = threadIdx.x;
  const int wid = tid >> 5;
  const int lane = tid & 31;

  const int ntt = 4 * (qb + 1);        // 64-key tiles for this q-block
  const int nt  = (ntt - sp + 3) / 4;  // tiles for this split (>=1)

  float o[8][4];
  #pragma unroll
  for (int nf = 0; nf < 8; nf++)
    #pragma unroll
    for (int c = 0; c < 4; c++) o[nf][c] = 0.f;
  float m0 = NEG_BIG, m1 = NEG_BIG, l0 = 0.f, l1 = 0.f;

  const int erow = lane >> 2;
  const int ecol = (lane & 3) * 2;

  const uint32_t sb  = smem_u32(dsmem);
  const uint32_t QHI = sb, QLO = sb + Q_BYTES;
  const uint32_t KVB = sb + 2 * Q_BYTES;

  // ---- stage Q (group 0) ----
  {
    const int rbase = b * TT + qb * QBLK;
    #pragma unroll
    for (int i = 0; i < 8; i++) {
      int gid = i * 512 + tid;               // 0..4095
      int arr = gid >> 11;                   // 0=hi,1=lo
      int g2 = gid & 2047;
      int row = g2 >> 3, ch = g2 & 7;
      const __nv_bfloat16* src = (arr ? g_qlo : g_qhi) + (size_t)(rbase + row) * DD + ch * 8;
      cpasync16u((arr ? QLO : QHI) + (uint32_t)(row * APITCH + ch * 16), src);
    }
    cp_commit();
  }

  auto issueKV = [&](int j, int st) {
    const int k0 = j * 64;
    const uint32_t base = KVB + (uint32_t)st * KV_STAGE;
    #pragma unroll
    for (int i = 0; i < 4; i++) {
      int gid = i * 512 + tid;               // 0..2047
      int arr = gid >> 9;                    // 0=Khi,1=Klo,2=Vhi,3=Vlo
      int g2 = gid & 511;
      int row = g2 >> 3, ch = g2 & 7;
      const __nv_bfloat16* ap =
          (arr == 0) ? g_khi : (arr == 1) ? g_klo : (arr == 2) ? g_vhi : g_vlo;
      const __nv_bfloat16* src = ap + (size_t)(b * TT + k0 + row) * DD + ch * 8;
      cpasync16u(base + (uint32_t)(arr * KV_ARR + row * APITCH + ch * 16), src);
    }
    cp_commit();
  };

  issueKV(sp, 0);          // group 1
  cp_wait1();              // Q (group 0) done
  __syncthreads();

  // ---- Q hi fragments register-resident; Q lo re-loaded per tile ----
  const uint32_t qoff = (uint32_t)((wid * 16 + (lane & 15)) * APITCH + (lane >> 4) * 16);
  uint32_t qh[4][4];
  #pragma unroll
  for (int ks = 0; ks < 4; ks++) ldm4(qh[ks], QHI + qoff + ks * 32);

  const uint32_t koff = (uint32_t)((((lane >> 4) & 1) * 8 + (lane & 7)) * APITCH + ((lane >> 3) & 1) * 16);
  const uint32_t voff = (uint32_t)((((lane >> 3) & 1) * 8 + (lane & 7)) * APITCH + ((lane >> 4) & 1) * 16);

  const int qlo_w = qb * QBLK + wid * 16;   // this warp's lowest query

  for (int tix = 0; tix < nt; tix++) {
    const int j  = sp + tix * 4;
    const int st = tix & 1;
    const int k0 = j * 64;
    cp_wait0();
    __syncthreads();
    if (tix + 1 < nt) issueKV(sp + (tix + 1) * 4, st ^ 1);

    if (k0 > qlo_w + 15) continue;   // whole tile above this warp's diagonal

    const uint32_t stage = KVB + (uint32_t)st * KV_STAGE;
    const uint32_t KH = stage, KL = stage + KV_ARR;
    const uint32_t VH = stage + 2 * KV_ARR, VL = stage + 3 * KV_ARR;

    // ---- S = Q K^T (3 terms) ----
    float s[8][4];
    #pragma unroll
    for (int nf = 0; nf < 8; nf++)
      #pragma unroll
      for (int c = 0; c < 4; c++) s[nf][c] = 0.f;

    #pragma unroll
    for (int ks = 0; ks < 4; ks++) {
      uint32_t ql[4];
      ldm4(ql, QLO + qoff + ks * 32);
      #pragma unroll
      for (int g = 0; g < 4; g++) {
        uint32_t bh[4], bl[4];
        uint32_t off = koff + (uint32_t)(g * 16 * APITCH + ks * 32);
        ldm4(bh, KH + off);
        ldm4(bl, KL + off);
        mma16816(s[2*g],   qh[ks], bh[0], bh[1]);
        mma16816(s[2*g+1], qh[ks], bh[2], bh[3]);
        mma16816(s[2*g],   qh[ks], bl[0], bl[1]);
        mma16816(s[2*g+1], qh[ks], bl[2], bl[3]);
        mma16816(s[2*g],   ql,     bh[0], bh[1]);
        mma16816(s[2*g+1], ql,     bh[2], bh[3]);
      }
    }

    // ---- causal mask (diagonal tiles only) ----
    if (k0 + 63 > qlo_w) {
      const int rlo = qlo_w + erow;
      #pragma unroll
      for (int nf = 0; nf < 8; nf++) {
        int key = k0 + nf * 8 + ecol;
        if (key     > rlo)     s[nf][0] = MASK_S;
        if (key + 1 > rlo)     s[nf][1] = MASK_S;
        if (key     > rlo + 8) s[nf][2] = MASK_S;
        if (key + 1 > rlo + 8) s[nf][3] = MASK_S;
      }
    }

    // ---- online softmax (fragment rows: l/4 and l/4+8) ----
    float r0 = fmaxf(s[0][0], s[0][1]);
    float r1 = fmaxf(s[0][2], s[0][3]);
    #pragma unroll
    for (int nf = 1; nf < 8; nf++) {
      r0 = fmaxf(r0, fmaxf(s[nf][0], s[nf][1]));
      r1 = fmaxf(r1, fmaxf(s[nf][2], s[nf][3]));
    }
    r0 = fmaxf(r0, __shfl_xor_sync(0xffffffffu, r0, 1));
    r0 = fmaxf(r0, __shfl_xor_sync(0xffffffffu, r0, 2));
    r1 = fmaxf(r1, __shfl_xor_sync(0xffffffffu, r1, 1));
    r1 = fmaxf(r1, __shfl_xor_sync(0xffffffffu, r1, 2));
    float mn0 = fmaxf(m0, r0), mn1 = fmaxf(m1, r1);
    float cr0 = __expf(m0 - mn0), cr1 = __expf(m1 - mn1);
    l0 *= cr0; l1 *= cr1; m0 = mn0; m1 = mn1;
    #pragma unroll
    for (int nf = 0; nf < 8; nf++) {
      o[nf][0] *= cr0; o[nf][1] *= cr0;
      o[nf][2] *= cr1; o[nf][3] *= cr1;
    }

    // ---- exp in place + row sums ----
    float sum0 = 0.f, sum1 = 0.f;
    #pragma unroll
    for (int nf = 0; nf < 8; nf++) {
      s[nf][0] = __expf(s[nf][0] - m0);
      s[nf][1] = __expf(s[nf][1] - m0);
      s[nf][2] = __expf(s[nf][2] - m1);
      s[nf][3] = __expf(s[nf][3] - m1);
      sum0 += s[nf][0] + s[nf][1];
      sum1 += s[nf][2] + s[nf][3];
    }
    sum0 += __shfl_xor_sync(0xffffffffu, sum0, 1);
    sum0 += __shfl_xor_sync(0xffffffffu, sum0, 2);
    sum1 += __shfl_xor_sync(0xffffffffu, sum1, 1);
    sum1 += __shfl_xor_sync(0xffffffffu, sum1, 2);
    l0 += sum0; l1 += sum1;

    // ---- O += P V (3 terms, P split built per kk, V via trans-ldmatrix) ----
    #pragma unroll
    for (int kk = 0; kk < 4; kk++) {
      uint32_t ah[4], al[4];
      bf16split2(s[2*kk][0],   s[2*kk][1],   ah[0], al[0]);
      bf16split2(s[2*kk][2],   s[2*kk][3],   ah[1], al[1]);
      bf16split2(s[2*kk+1][0], s[2*kk+1][1], ah[2], al[2]);
      bf16split2(s[2*kk+1][2], s[2*kk+1][3], ah[3], al[3]);
      #pragma unroll
      for (int dg = 0; dg < 4; dg++) {
        uint32_t vh[4], vl[4];
        uint32_t off = voff + (uint32_t)(kk * 16 * APITCH + dg * 32);
        ldm4t(vh, VH + off);
        ldm4t(vl, VL + off);
        mma16816(o[2*dg],   ah, vh[0], vh[1]);
        mma16816(o[2*dg+1], ah, vh[2], vh[3]);
        mma16816(o[2*dg],   ah, vl[0], vl[1]);
        mma16816(o[2*dg+1], ah, vl[2], vl[3]);
        mma16816(o[2*dg],   al, vh[0], vh[1]);
        mma16816(o[2*dg+1], al, vh[2], vh[3]);
      }
    }
  }

  // ---- epilogue: partials ----
  {
    const int row0g = b * TT + qb * QBLK + wid * 16 + erow;
    size_t pr0 = (size_t)sp * ROWS + row0g;
    size_t pr1 = pr0 + 8;
    if ((lane & 3) == 0) {
      g_pml[(size_t)row0g * 8 + sp]       = m0;
      g_pml[(size_t)row0g * 8 + 4 + sp]   = l0;
      g_pml[(size_t)(row0g + 8) * 8 + sp]     = m1;
      g_pml[(size_t)(row0g + 8) * 8 + 4 + sp] = l1;
    }
    #pragma unroll
    for (int nf = 0; nf < 8; nf++) {
      int col = nf * 8 + ecol;
      *(float2*)(g_po + pr0 * DD + col) = make_float2(o[nf][0], o[nf][1]);
      *(float2*)(g_po + pr1 * DD + col) = make_float2(o[nf][2], o[nf][3]);
    }
  }
}

// ---------------------------------------------------------------------------
// Kernel 3: LSE combine. One thread per output float4. grid=1024.
// ---------------------------------------------------------------------------
__global__ __launch_bounds__(256) void combine_kernel(float* __restrict__ out)
{
  int gid = blockIdx.x * 256 + threadIdx.x;   // 0 .. ROWS*16-1
  int r  = gid >> 4;
  int c  = (gid & 15) * 4;

  float4 m4 = *(const float4*)&g_pml[(size_t)r * 8];
  float4 l4 = *(const float4*)&g_pml[(size_t)r * 8 + 4];
  float mm[4] = { m4.x, m4.y, m4.z, m4.w };
  float ll[4] = { l4.x, l4.y, l4.z, l4.w };

  float M = fmaxf(fmaxf(mm[0], mm[1]), fmaxf(mm[2], mm[3]));
  float w[S_SPLIT]; float L = 0.f;
  #pragma unroll
  for (int s = 0; s < S_SPLIT; s++) { w[s] = __expf(mm[s] - M); L += ll[s] * w[s]; }
  float inv = 1.0f / L;

  float4 acc = make_float4(0.f, 0.f, 0.f, 0.f);
  #pragma unroll
  for (int s = 0; s < S_SPLIT; s++) {
    float4 p = *(const float4*)(g_po + ((size_t)s * ROWS + r) * DD + c);
    acc.x += p.x * w[s]; acc.y += p.y * w[s];
    acc.z += p.z * w[s]; acc.w += p.w * w[s];
  }
  acc.x *= inv; acc.y *= inv; acc.z *= inv; acc.w *= inv;
  *(float4*)(out + (size_t)r * DD + c) = acc;
}

// ---------------------------------------------------------------------------
extern "C" void kernel_launch(void* const* d_in, const int* in_sizes, int n_in,
                              void* d_out, int out_size)
{
  const float* x  = (const float*)d_in[0];
  const float* Wk = (const float*)d_in[1];
  const float* Wq = (const float*)d_in[2];
  const float* Wv = (const float*)d_in[3];
  float* out = (float*)d_out;

  cudaFuncSetAttribute(proj_mma, cudaFuncAttributeMaxDynamicSharedMemorySize, SMEM_PROJ);
  cudaFuncSetAttribute(attn_mma, cudaFuncAttributeMaxDynamicSharedMemorySize, SMEM_ATT);

  prep_w<<<NTOT, 256>>>(Wk, Wq, Wv);
  proj_mma<<<ROWS / 128, 512, SMEM_PROJ>>>(x);
  attn_mma<<<dim3(TT / QBLK, BB, S_SPLIT), 512, SMEM_ATT>>>();
  combine_kernel<<<ROWS * 16 / 256, 256>>>(out);
}

// round 10
// speedup vs baseline: 1.6827x; 1.6827x over previous
#include <cuda_runtime.h>
#include <cuda_bf16.h>
#include <cstdint>

// Problem dims (fixed by reference)
#define BB 8
#define TT 2048
#define CC 1024
#define DD 64
#define ROWS (BB*TT)      // 16384
#define S_SPLIT 4
#define NEG_BIG  (-1.0e30f)
#define MASK_S   (-3.0e38f)

#define NTOT 192          // fused proj cols: 64 K | 64 Q | 64 V
#define KC 64             // K-chunk per pipeline stage (bf16 elems)
#define NCHUNK (CC/KC)    // 16

// proj smem: rows of 64 bf16 = 128B + 16B pad -> 144B pitch (LDSM conflict-free)
#define PPITCH 144
#define XH_BYTES (128*PPITCH)            // 18432
#define WH_BYTES (NTOT*PPITCH)           // 27648
#define STAGE_BYTES (2*XH_BYTES + 2*WH_BYTES)   // 92160
#define SMEM_PROJ (2*STAGE_BYTES)               // 184320

// attn smem: bf16 pitch 72 elems = 144B
#define APITCH 144
#define Q_BYTES (128*APITCH)        // 18432 per array
#define KV_ARR  (64*APITCH)         // 9216 per array
#define KV_STAGE (4*KV_ARR)         // 36864 (Khi,Klo,Vhi,Vlo)
#define SMEM_ATT (2*Q_BYTES + 2*KV_STAGE)   // 110592

// Scratch (allocation-free: __device__ globals)
__device__ float g_po[S_SPLIT*ROWS*DD];
__device__ float g_pm[S_SPLIT*ROWS];
__device__ float g_pl[S_SPLIT*ROWS];
__device__ __nv_bfloat16 g_wthi[NTOT*CC];
__device__ __nv_bfloat16 g_wtlo[NTOT*CC];
__device__ __nv_bfloat16 g_qhi[ROWS*DD], g_qlo[ROWS*DD];
__device__ __nv_bfloat16 g_khi[ROWS*DD], g_klo[ROWS*DD];
__device__ __nv_bfloat16 g_vhi[ROWS*DD], g_vlo[ROWS*DD];

__device__ __forceinline__ void cpasync16u(uint32_t sa, const void* g){
  asm volatile("cp.async.cg.shared.global [%0], [%1], 16;\n" :: "r"(sa), "l"(g) : "memory");
}
__device__ __forceinline__ void cp_commit(){ asm volatile("cp.async.commit_group;\n" ::: "memory"); }
__device__ __forceinline__ void cp_wait0(){ asm volatile("cp.async.wait_group 0;\n" ::: "memory"); }
__device__ __forceinline__ void cp_wait1(){ asm volatile("cp.async.wait_group 1;\n" ::: "memory"); }

__device__ __forceinline__ uint32_t smem_u32(const void* p){
  return (uint32_t)__cvta_generic_to_shared(p);
}
__device__ __forceinline__ void ldm4(uint32_t* r, uint32_t addr){
  asm volatile("ldmatrix.sync.aligned.m8n8.x4.shared.b16 {%0,%1,%2,%3},[%4];"
    : "=r"(r[0]), "=r"(r[1]), "=r"(r[2]), "=r"(r[3]) : "r"(addr));
}
__device__ __forceinline__ void ldm4t(uint32_t* r, uint32_t addr){
  asm volatile("ldmatrix.sync.aligned.m8n8.x4.trans.shared.b16 {%0,%1,%2,%3},[%4];"
    : "=r"(r[0]), "=r"(r[1]), "=r"(r[2]), "=r"(r[3]) : "r"(addr));
}
__device__ __forceinline__ void mma16816(float* d, const uint32_t* a,
                                         uint32_t b0, uint32_t b1){
  asm volatile("mma.sync.aligned.m16n8k16.row.col.f32.bf16.bf16.f32 "
    "{%0,%1,%2,%3},{%4,%5,%6,%7},{%8,%9},{%0,%1,%2,%3};"
    : "+f"(d[0]), "+f"(d[1]), "+f"(d[2]), "+f"(d[3])
    : "r"(a[0]), "r"(a[1]), "r"(a[2]), "r"(a[3]), "r"(b0), "r"(b1));
}
// pack (a -> low half, b -> high half) with exact fp32 residual in lo
__device__ __forceinline__ void bf16split2(float a, float b, uint32_t &hi, uint32_t &lo){
  asm("cvt.rn.bf16x2.f32 %0, %1, %2;" : "=r"(hi) : "f"(b), "f"(a));
  float fa = __uint_as_float(hi << 16);
  float fb = __uint_as_float(hi & 0xffff0000u);
  asm("cvt.rn.bf16x2.f32 %0, %1, %2;" : "=r"(lo) : "f"(b - fb), "f"(a - fa));
}

// ---------------------------------------------------------------------------
// Kernel 0: split W into bf16 hi/lo, transposed [n][k].
// ---------------------------------------------------------------------------
__global__ __launch_bounds__(256) void prep_w(
    const float* __restrict__ Wk, const float* __restrict__ Wq,
    const float* __restrict__ Wv)
{
  int n = blockIdx.x;
  const float* W = (n < 64) ? Wk : ((n < 128) ? Wq : Wv);
  int col = n & 63;
  for (int k = threadIdx.x; k < CC; k += 256) {
    float w = W[(size_t)k * DD + col];
    __nv_bfloat16 h = __float2bfloat16(w);
    __nv_bfloat16 l = __float2bfloat16(w - __bfloat162float(h));
    g_wthi[n * CC + k] = h;
    g_wtlo[n * CC + k] = l;
  }
}

// ---------------------------------------------------------------------------
// Kernel 1: QKV projection via mma.sync (3-term split). 256 threads, 8 warps,
// warp tile 32x96 (R8 config), K-chunk 64 (4 k16 steps), double-buffered.
// Epilogue writes bf16 hi/lo Q(pre-scaled 0.125)/K/V.
// ---------------------------------------------------------------------------
extern __shared__ char dsmem[];

__global__ __launch_bounds__(256) void proj_mma(const float* __restrict__ x)
{
  const int tid  = threadIdx.x;
  const int wid  = tid >> 5;
  const int lane = tid & 31;
  const int rowBase = blockIdx.x * 128;

  const uint32_t sbase = smem_u32(dsmem);
  auto xhiB = [&](int st){ return sbase + (uint32_t)st * STAGE_BYTES; };
  auto xloB = [&](int st){ return xhiB(st) + XH_BYTES; };
  auto whiB = [&](int st){ return xhiB(st) + 2 * XH_BYTES; };
  auto wloB = [&](int st){ return whiB(st) + WH_BYTES; };

  const int wm = (wid & 3) * 32;
  const int wn = (wid >> 2) * 96;

  const int aRow = wm + ((lane >> 3) & 1) * 8 + (lane & 7);
  const int aK   = (lane >> 4) * 8;
  const uint32_t aOff = (uint32_t)(aRow * PPITCH + aK * 2);
  const int bN = wn + ((lane >> 4) & 1) * 8 + (lane & 7);
  const int bK = ((lane >> 3) & 1) * 8;
  const uint32_t bOff = (uint32_t)(bN * PPITCH + bK * 2);

  float d[2][12][4];
  #pragma unroll
  for (int mf = 0; mf < 2; mf++)
    #pragma unroll
    for (int nf = 0; nf < 12; nf++)
      #pragma unroll
      for (int c = 0; c < 4; c++) d[mf][nf][c] = 0.f;

  // x chunk: 128 rows x 64 cols fp32 = 2048 float4; 8 per thread
  float4 xr[8];
  auto loadX = [&](int chunk) {
    const int k0 = chunk * KC;
    #pragma unroll
    for (int i = 0; i < 8; i++) {
      int f = i * 256 + tid;            // 0..2047
      int row = f >> 4, c4 = (f & 15) * 4;
      xr[i] = *(const float4*)(x + (size_t)(rowBase + row) * CC + k0 + c4);
    }
  };
  auto convertX = [&](int st) {
    const uint32_t xh = xhiB(st), xl = xloB(st);
    #pragma unroll
    for (int i = 0; i < 8; i++) {
      int f = i * 256 + tid;
      int row = f >> 4;
      uint32_t boff = (uint32_t)(row * PPITCH + (f & 15) * 8);
      float4 v = xr[i];
      uint32_t h01, h23, l01, l23;
      bf16split2(v.x, v.y, h01, l01);
      bf16split2(v.z, v.w, h23, l23);
      asm volatile("st.shared.v2.b32 [%0], {%1,%2};" :: "r"(xh + boff), "r"(h01), "r"(h23) : "memory");
      asm volatile("st.shared.v2.b32 [%0], {%1,%2};" :: "r"(xl + boff), "r"(l01), "r"(l23) : "memory");
    }
  };
  // W chunk: 192 rows x 64 bf16 = 8 x 16B per row, hi+lo = 3072 cp.async
  auto issueW = [&](int chunk, int st) {
    const int k0 = chunk * KC;
    const uint32_t wh = whiB(st), wl = wloB(st);
    #pragma unroll
    for (int i = 0; i < 12; i++) {
      int gid = i * 256 + tid;             // 0..3071
      int half = (gid >= 1536) ? 1 : 0;
      int g2 = gid - half * 1536;
      int n = g2 >> 3, c = g2 & 7;
      const __nv_bfloat16* src =
          (half ? g_wtlo : g_wthi) + (size_t)n * CC + k0 + c * 8;
      uint32_t dst = (half ? wl : wh) + (uint32_t)(n * PPITCH + c * 16);
      cpasync16u(dst, src);
    }
    cp_commit();
  };

  loadX(0);
  issueW(0, 0);
  convertX(0);
  loadX(1);

  for (int it = 0; it < NCHUNK; it++) {
    const int cur = it & 1;
    cp_wait0();
    __syncthreads();
    if (it + 1 < NCHUNK) issueW(it + 1, cur ^ 1);

    #pragma unroll
    for (int ks = 0; ks < 4; ks++) {
      uint32_t ahi[2][4], alo[2][4];
      #pragma unroll
      for (int mf = 0; mf < 2; mf++) {
        ldm4(ahi[mf], xhiB(cur) + aOff + (uint32_t)(mf * 16 * PPITCH + ks * 32));
        ldm4(alo[mf], xloB(cur) + aOff + (uint32_t)(mf * 16 * PPITCH + ks * 32));
      }
      #pragma unroll
      for (int nf2 = 0; nf2 < 6; nf2++) {
        uint32_t bhi[4], blo[4];
        uint32_t off = bOff + (uint32_t)(nf2 * 16 * PPITCH + ks * 32);
        ldm4(bhi, whiB(cur) + off);
        ldm4(blo, wloB(cur) + off);
        #pragma unroll
        for (int mf = 0; mf < 2; mf++) {
          #pragma unroll
          for (int s = 0; s < 2; s++) {
            float* dd = d[mf][2 * nf2 + s];
            mma16816(dd, ahi[mf], bhi[2 * s], bhi[2 * s + 1]);
            mma16816(dd, ahi[mf], blo[2 * s], blo[2 * s + 1]);
            mma16816(dd, alo[mf], bhi[2 * s], bhi[2 * s + 1]);
          }
        }
      }
    }

    if (it + 1 < NCHUNK) convertX(cur ^ 1);
    if (it + 2 < NCHUNK) loadX(it + 2);
  }

  // epilogue: split fp32 results to bf16 hi/lo gmem (Q scaled by 0.125)
  const int erow = lane >> 2;
  const int ecol = (lane & 3) * 2;
  #pragma unroll
  for (int mf = 0; mf < 2; mf++) {
    #pragma unroll
    for (int nf = 0; nf < 12; nf++) {
      int n0 = wn + nf * 8;
      int part = n0 >> 6;
      __nv_bfloat16* hp = (part == 0) ? g_khi : ((part == 1) ? g_qhi : g_vhi);
      __nv_bfloat16* lp = (part == 0) ? g_klo : ((part == 1) ? g_qlo : g_vlo);
      float sc = (part == 1) ? 0.125f : 1.0f;
      int col = (n0 & 63) + ecol;
      size_t r0 = (size_t)(rowBase + wm + mf * 16 + erow);
      uint32_t h, l2;
      bf16split2(d[mf][nf][0] * sc, d[mf][nf][1] * sc, h, l2);
      *(uint32_t*)(hp + r0 * DD + col) = h;
      *(uint32_t*)(lp + r0 * DD + col) = l2;
      bf16split2(d[mf][nf][2] * sc, d[mf][nf][3] * sc, h, l2);
      *(uint32_t*)(hp + (r0 + 8) * DD + col) = h;
      *(uint32_t*)(lp + (r0 + 8) * DD + col) = l2;
    }
  }
}

// ---------------------------------------------------------------------------
// Kernel 2: FlashAttention-2 on mma.sync (R8 config: 256 thr, 8 warps,
// 128-query blocks) + HEAVY-FIRST qb order. Strided split-KV (tile j ->
// split j%4). 3-term bf16 split for QK^T and PV. Double-buffered cp.async.
// ---------------------------------------------------------------------------
__global__ __launch_bounds__(256) void attn_mma()
{
  const int qb  = (TT / 128 - 1) - blockIdx.x;   // heavy-first
  const int b   = blockIdx.y;
  const int sp  = blockIdx.z;
  const int tid = threadIdx.x;
  const int wid = tid >> 5;
  const int lane = tid & 31;

  const int ntt = 2 * (qb + 1);        // total 64-key tiles for this q-block
  const int nt  = (ntt > sp) ? (ntt - sp + 3) / 4 : 0;

  float o[8][4];
  #pragma unroll
  for (int nf = 0; nf < 8; nf++)
    #pragma unroll
    for (int c = 0; c < 4; c++) o[nf][c] = 0.f;
  float m0 = NEG_BIG, m1 = NEG_BIG, l0 = 0.f, l1 = 0.f;

  const int erow = lane >> 2;
  const int ecol = (lane & 3) * 2;
  const int row0g = b * TT + qb * 128 + wid * 16 + erow;   // global row (lo)

  if (nt == 0) goto epilogue;

  {
    const uint32_t sb  = smem_u32(dsmem);
    const uint32_t QHI = sb, QLO = sb + Q_BYTES;
    const uint32_t KVB = sb + 2 * Q_BYTES;

    // ---- stage Q (group 0) ----
    {
      const int rbase = b * TT + qb * 128;
      #pragma unroll
      for (int i = 0; i < 8; i++) {
        int gid = i * 256 + tid;               // 0..2047
        int arr = gid >> 10;                   // 0=hi,1=lo
        int g2 = gid & 1023;
        int row = g2 >> 3, ch = g2 & 7;
        const __nv_bfloat16* src = (arr ? g_qlo : g_qhi) + (size_t)(rbase + row) * DD + ch * 8;
        cpasync16u((arr ? QLO : QHI) + (uint32_t)(row * APITCH + ch * 16), src);
      }
      cp_commit();
    }

    auto issueKV = [&](int j, int st) {
      const int k0 = j * 64;
      const uint32_t base = KVB + (uint32_t)st * KV_STAGE;
      #pragma unroll
      for (int i = 0; i < 8; i++) {
        int gid = i * 256 + tid;               // 0..2047
        int arr = gid >> 9;                    // 0=Khi,1=Klo,2=Vhi,3=Vlo
        int g2 = gid & 511;
        int row = g2 >> 3, ch = g2 & 7;
        const __nv_bfloat16* ap =
            (arr == 0) ? g_khi : (arr == 1) ? g_klo : (arr == 2) ? g_vhi : g_vlo;
        const __nv_bfloat16* src = ap + (size_t)(b * TT + k0 + row) * DD + ch * 8;
        cpasync16u(base + (uint32_t)(arr * KV_ARR + row * APITCH + ch * 16), src);
      }
      cp_commit();
    };

    issueKV(sp, 0);          // group 1
    cp_wait1();              // Q (group 0) done
    __syncthreads();

    // ---- Q fragments (register-resident) ----
    const uint32_t qoff = (uint32_t)((wid * 16 + (lane & 15)) * APITCH + (lane >> 4) * 16);
    uint32_t qh[4][4], ql[4][4];
    #pragma unroll
    for (int ks = 0; ks < 4; ks++) {
      ldm4(qh[ks], QHI + qoff + ks * 32);
      ldm4(ql[ks], QLO + qoff + ks * 32);
    }

    const uint32_t koff = (uint32_t)((((lane >> 4) & 1) * 8 + (lane & 7)) * APITCH + ((lane >> 3) & 1) * 16);
    const uint32_t voff = (uint32_t)((((lane >> 3) & 1) * 8 + (lane & 7)) * APITCH + ((lane >> 4) & 1) * 16);

    for (int tix = 0; tix < nt; tix++) {
      const int j  = sp + tix * 4;
      const int st = tix & 1;
      const int k0 = j * 64;
      cp_wait0();
      __syncthreads();
      if (tix + 1 < nt) issueKV(sp + (tix + 1) * 4, st ^ 1);

      const uint32_t stage = KVB + (uint32_t)st * KV_STAGE;
      const uint32_t KH = stage, KL = stage + KV_ARR;
      const uint32_t VH = stage + 2 * KV_ARR, VL = stage + 3 * KV_ARR;

      // ---- S = Q K^T (3 terms) ----
      float s[8][4];
      #pragma unroll
      for (int nf = 0; nf < 8; nf++)
        #pragma unroll
        for (int c = 0; c < 4; c++) s[nf][c] = 0.f;

      #pragma unroll
      for (int ks = 0; ks < 4; ks++) {
        #pragma unroll
        for (int g = 0; g < 4; g++) {
          uint32_t bh[4], bl[4];
          uint32_t off = koff + (uint32_t)(g * 16 * APITCH + ks * 32);
          ldm4(bh, KH + off);
          ldm4(bl, KL + off);
          mma16816(s[2*g],   qh[ks], bh[0], bh[1]);
          mma16816(s[2*g+1], qh[ks], bh[2], bh[3]);
          mma16816(s[2*g],   qh[ks], bl[0], bl[1]);
          mma16816(s[2*g+1], qh[ks], bl[2], bl[3]);
          mma16816(s[2*g],   ql[ks], bh[0], bh[1]);
          mma16816(s[2*g+1], ql[ks], bh[2], bh[3]);
        }
      }

      // ---- causal mask (only the diagonal tiles need it) ----
      if (k0 + 63 > qb * 128) {
        const int rlo = qb * 128 + wid * 16 + erow;
        #pragma unroll
        for (int nf = 0; nf < 8; nf++) {
          int key = k0 + nf * 8 + ecol;
          if (key     > rlo)     s[nf][0] = MASK_S;
          if (key + 1 > rlo)     s[nf][1] = MASK_S;
          if (key     > rlo + 8) s[nf][2] = MASK_S;
          if (key + 1 > rlo + 8) s[nf][3] = MASK_S;
        }
      }

      // ---- online softmax (fragment rows: l/4 and l/4+8) ----
      float r0 = fmaxf(s[0][0], s[0][1]);
      float r1 = fmaxf(s[0][2], s[0][3]);
      #pragma unroll
      for (int nf = 1; nf < 8; nf++) {
        r0 = fmaxf(r0, fmaxf(s[nf][0], s[nf][1]));
        r1 = fmaxf(r1, fmaxf(s[nf][2], s[nf][3]));
      }
      r0 = fmaxf(r0, __shfl_xor_sync(0xffffffffu, r0, 1));
      r0 = fmaxf(r0, __shfl_xor_sync(0xffffffffu, r0, 2));
      r1 = fmaxf(r1, __shfl_xor_sync(0xffffffffu, r1, 1));
      r1 = fmaxf(r1, __shfl_xor_sync(0xffffffffu, r1, 2));
      float mn0 = fmaxf(m0, r0), mn1 = fmaxf(m1, r1);
      float cr0 = __expf(m0 - mn0), cr1 = __expf(m1 - mn1);
      l0 *= cr0; l1 *= cr1; m0 = mn0; m1 = mn1;
      #pragma unroll
      for (int nf = 0; nf < 8; nf++) {
        o[nf][0] *= cr0; o[nf][1] *= cr0;
        o[nf][2] *= cr1; o[nf][3] *= cr1;
      }

      // ---- exp, row sums, P -> A-frag bf16 hi/lo ----
      float sum0 = 0.f, sum1 = 0.f;
      uint32_t ph[4][4], pl4[4][4];
      #pragma unroll
      for (int nf = 0; nf < 8; nf++) {
        float p0 = __expf(s[nf][0] - m0);
        float p1 = __expf(s[nf][1] - m0);
        float p2 = __expf(s[nf][2] - m1);
        float p3 = __expf(s[nf][3] - m1);
        sum0 += p0 + p1; sum1 += p2 + p3;
        int kk = nf >> 1, bs = (nf & 1) * 2;
        bf16split2(p0, p1, ph[kk][bs],     pl4[kk][bs]);
        bf16split2(p2, p3, ph[kk][bs + 1], pl4[kk][bs + 1]);
      }
      sum0 += __shfl_xor_sync(0xffffffffu, sum0, 1);
      sum0 += __shfl_xor_sync(0xffffffffu, sum0, 2);
      sum1 += __shfl_xor_sync(0xffffffffu, sum1, 1);
      sum1 += __shfl_xor_sync(0xffffffffu, sum1, 2);
      l0 += sum0; l1 += sum1;

      // ---- O += P V (3 terms, V via trans-ldmatrix) ----
      #pragma unroll
      for (int kk = 0; kk < 4; kk++) {
        #pragma unroll
        for (int dg = 0; dg < 4; dg++) {
          uint32_t vh[4], vl[4];
          uint32_t off = voff + (uint32_t)(kk * 16 * APITCH + dg * 32);
          ldm4t(vh, VH + off);
          ldm4t(vl, VL + off);
          mma16816(o[2*dg],   ph[kk],  vh[0], vh[1]);
          mma16816(o[2*dg+1], ph[kk],  vh[2], vh[3]);
          mma16816(o[2*dg],   ph[kk],  vl[0], vl[1]);
          mma16816(o[2*dg+1], ph[kk],  vl[2], vl[3]);
          mma16816(o[2*dg],   pl4[kk], vh[0], vh[1]);
          mma16816(o[2*dg+1], pl4[kk], vh[2], vh[3]);
        }
      }
    }
  }

epilogue:
  {
    size_t pr0 = (size_t)sp * ROWS + row0g;
    size_t pr1 = pr0 + 8;
    if ((lane & 3) == 0) {
      g_pm[pr0] = m0; g_pl[pr0] = l0;
      g_pm[pr1] = m1; g_pl[pr1] = l1;
    }
    #pragma unroll
    for (int nf = 0; nf < 8; nf++) {
      int col = nf * 8 + ecol;
      *(float2*)(g_po + pr0 * DD + col) = make_float2(o[nf][0], o[nf][1]);
      *(float2*)(g_po + pr1 * DD + col) = make_float2(o[nf][2], o[nf][3]);
    }
  }
}

// ---------------------------------------------------------------------------
// Kernel 3: LSE combine. One thread per output float4. grid=1024.
// ---------------------------------------------------------------------------
__global__ __launch_bounds__(256) void combine_kernel(float* __restrict__ out)
{
  int gid = blockIdx.x * 256 + threadIdx.x;   // 0 .. ROWS*16-1
  int r  = gid >> 4;
  int c  = (gid & 15) * 4;

  float m[S_SPLIT], l[S_SPLIT];
  #pragma unroll
  for (int s = 0; s < S_SPLIT; s++) {
    m[s] = g_pm[(size_t)s * ROWS + r];
    l[s] = g_pl[(size_t)s * ROWS + r];
  }
  float M = fmaxf(fmaxf(m[0], m[1]), fmaxf(m[2], m[3]));
  float w[S_SPLIT]; float L = 0.f;
  #pragma unroll
  for (int s = 0; s < S_SPLIT; s++) { w[s] = __expf(m[s] - M); L += l[s] * w[s]; }
  float inv = 1.0f / L;

  float4 acc = make_float4(0.f, 0.f, 0.f, 0.f);
  #pragma unroll
  for (int s = 0; s < S_SPLIT; s++) {
    float4 p = *(const float4*)(g_po + ((size_t)s * ROWS + r) * DD + c);
    acc.x += p.x * w[s]; acc.y += p.y * w[s];
    acc.z += p.z * w[s]; acc.w += p.w * w[s];
  }
  acc.x *= inv; acc.y *= inv; acc.z *= inv; acc.w *= inv;
  *(float4*)(out + (size_t)r * DD + c) = acc;
}

// ---------------------------------------------------------------------------
extern "C" void kernel_launch(void* const* d_in, const int* in_sizes, int n_in,
                              void* d_out, int out_size)
{
  const float* x  = (const float*)d_in[0];
  const float* Wk = (const float*)d_in[1];
  const float* Wq = (const float*)d_in[2];
  const float* Wv = (const float*)d_in[3];
  float* out = (float*)d_out;

  cudaFuncSetAttribute(proj_mma, cudaFuncAttributeMaxDynamicSharedMemorySize, SMEM_PROJ);
  cudaFuncSetAttribute(attn_mma, cudaFuncAttributeMaxDynamicSharedMemorySize, SMEM_ATT);

  prep_w<<<NTOT, 256>>>(Wk, Wq, Wv);
  proj_mma<<<ROWS / 128, 256, SMEM_PROJ>>>(x);
  attn_mma<<<dim3(TT / 128, BB, S_SPLIT), 256, SMEM_ATT>>>();
  combine_kernel<<<ROWS * 16 / 256, 256>>>(out);
}

// round 11
// speedup vs baseline: 2.5040x; 1.4881x over previous
#include <cuda_runtime.h>
#include <cuda_fp16.h>
#include <cstdint>

// Problem dims (fixed by reference)
#define BB 8
#define TT 2048
#define CC 1024
#define DD 64
#define ROWS (BB*TT)      // 16384
#define S_SPLIT 4
#define NEG_BIG  (-1.0e30f)
#define MASK_S   (-3.0e38f)

#define NTOT 192          // fused proj cols: 64 K | 64 Q | 64 V
#define KC 64             // K-chunk per pipeline stage (fp16 elems)
#define NCHUNK (CC/KC)    // 16

// proj smem: rows of 64 fp16 = 128B + 16B pad -> 144B pitch
#define PPITCH 144
#define PM 64                             // rows per proj CTA
#define XH_BYTES (PM*PPITCH)              // 9216
#define WH_BYTES (NTOT*PPITCH)            // 27648
#define STAGE_BYTES (2*XH_BYTES + WH_BYTES)   // 46080 (xh, xl, w)
#define SMEM_PROJ (2*STAGE_BYTES)             // 92160 -> 2 CTAs/SM

// attn smem
#define APITCH 144
#define Q_BYTES (128*APITCH)        // 18432 (Q single fp16)
#define KV_ARR  (64*APITCH)         // 9216
#define KV_STAGE (3*KV_ARR)         // 27648 (K, Vhi, Vlo)
#define SMEM_ATT (Q_BYTES + 2*KV_STAGE)   // 73728 -> 2 CTAs/SM

// Scratch (allocation-free: __device__ globals)
__device__ float g_po[S_SPLIT*ROWS*DD];
__device__ float g_pm[S_SPLIT*ROWS];
__device__ float g_pl[S_SPLIT*ROWS];
__device__ __half g_wth[NTOT*CC];           // W^T fp16 single, [n][k]
__device__ __half g_qh[ROWS*DD];            // Q fp16 (pre-scaled 0.125)
__device__ __half g_kh[ROWS*DD];            // K fp16
__device__ __half g_vh[ROWS*DD], g_vl[ROWS*DD];   // V fp16 hi/lo

__device__ __forceinline__ void cpasync16u(uint32_t sa, const void* g){
  asm volatile("cp.async.cg.shared.global [%0], [%1], 16;\n" :: "r"(sa), "l"(g) : "memory");
}
__device__ __forceinline__ void cp_commit(){ asm volatile("cp.async.commit_group;\n" ::: "memory"); }
__device__ __forceinline__ void cp_wait0(){ asm volatile("cp.async.wait_group 0;\n" ::: "memory"); }
__device__ __forceinline__ void cp_wait1(){ asm volatile("cp.async.wait_group 1;\n" ::: "memory"); }

__device__ __forceinline__ uint32_t smem_u32(const void* p){
  return (uint32_t)__cvta_generic_to_shared(p);
}
__device__ __forceinline__ void ldm4(uint32_t* r, uint32_t addr){
  asm volatile("ldmatrix.sync.aligned.m8n8.x4.shared.b16 {%0,%1,%2,%3},[%4];"
    : "=r"(r[0]), "=r"(r[1]), "=r"(r[2]), "=r"(r[3]) : "r"(addr));
}
__device__ __forceinline__ void ldm4t(uint32_t* r, uint32_t addr){
  asm volatile("ldmatrix.sync.aligned.m8n8.x4.trans.shared.b16 {%0,%1,%2,%3},[%4];"
    : "=r"(r[0]), "=r"(r[1]), "=r"(r[2]), "=r"(r[3]) : "r"(addr));
}
// fp16 mma: m16n8k16, f32 accum
__device__ __forceinline__ void mma16816h(float* d, const uint32_t* a,
                                          uint32_t b0, uint32_t b1){
  asm volatile("mma.sync.aligned.m16n8k16.row.col.f32.f16.f16.f32 "
    "{%0,%1,%2,%3},{%4,%5,%6,%7},{%8,%9},{%0,%1,%2,%3};"
    : "+f"(d[0]), "+f"(d[1]), "+f"(d[2]), "+f"(d[3])
    : "r"(a[0]), "r"(a[1]), "r"(a[2]), "r"(a[3]), "r"(b0), "r"(b1));
}
// pack (a -> low half, b -> high half) as f16x2
__device__ __forceinline__ uint32_t f16pack2(float a, float b){
  uint32_t r; asm("cvt.rn.f16x2.f32 %0, %1, %2;" : "=r"(r) : "f"(b), "f"(a));
  return r;
}
// fp16 split with exact fp32 residual in lo
__device__ __forceinline__ void f16split2(float a, float b, uint32_t &hi, uint32_t &lo){
  asm("cvt.rn.f16x2.f32 %0, %1, %2;" : "=r"(hi) : "f"(b), "f"(a));
  float fa, fb;
  asm("{ .reg .f16 l_, h_;\n\t mov.b32 {l_, h_}, %2;\n\t"
      "cvt.f32.f16 %0, l_;\n\t cvt.f32.f16 %1, h_;\n\t }"
      : "=f"(fa), "=f"(fb) : "r"(hi));
  asm("cvt.rn.f16x2.f32 %0, %1, %2;" : "=r"(lo) : "f"(b - fb), "f"(a - fa));
}

// ---------------------------------------------------------------------------
// Kernel 0: W -> fp16 single, transposed [n][k].
// ---------------------------------------------------------------------------
__global__ __launch_bounds__(256) void prep_w(
    const float* __restrict__ Wk, const float* __restrict__ Wq,
    const float* __restrict__ Wv)
{
  int n = blockIdx.x;
  const float* W = (n < 64) ? Wk : ((n < 128) ? Wq : Wv);
  int col = n & 63;
  for (int k = threadIdx.x; k < CC; k += 256)
    g_wth[n * CC + k] = __float2half(W[(size_t)k * DD + col]);
}

// ---------------------------------------------------------------------------
// Kernel 1: QKV projection, fp16 2-term (x = xh+xl split, W single).
// grid = 256 CTAs x 64 rows, 256 thr (8 warps), warp tile 16x96,
// KC=64 (4 k16 steps), double-buffered. Epilogue: Q single fp16 (x0.125),
// K single fp16, V fp16 hi/lo.
// ---------------------------------------------------------------------------
extern __shared__ char dsmem[];

__global__ __launch_bounds__(256, 2) void proj_mma(const float* __restrict__ x)
{
  const int tid  = threadIdx.x;
  const int wid  = tid >> 5;
  const int lane = tid & 31;
  const int rowBase = blockIdx.x * PM;

  const uint32_t sbase = smem_u32(dsmem);
  auto xhiB = [&](int st){ return sbase + (uint32_t)st * STAGE_BYTES; };
  auto xloB = [&](int st){ return xhiB(st) + XH_BYTES; };
  auto wB   = [&](int st){ return xhiB(st) + 2 * XH_BYTES; };

  const int wm = (wid & 3) * 16;       // 4 row groups x 16
  const int wn = (wid >> 2) * 96;      // 2 col groups x 96

  const uint32_t aOff = (uint32_t)((wm + (lane & 15)) * PPITCH + (lane >> 4) * 16);
  const int bN = wn + ((lane >> 4) & 1) * 8 + (lane & 7);
  const uint32_t bOff = (uint32_t)(bN * PPITCH + ((lane >> 3) & 1) * 16);

  float d[12][4];
  #pragma unroll
  for (int nf = 0; nf < 12; nf++)
    #pragma unroll
    for (int c = 0; c < 4; c++) d[nf][c] = 0.f;

  // x chunk: 64 rows x 64 cols fp32 = 1024 float4 -> 4/thread
  float4 xr[4];
  auto loadX = [&](int chunk) {
    const int k0 = chunk * KC;
    #pragma unroll
    for (int i = 0; i < 4; i++) {
      int f = i * 256 + tid;            // 0..1023
      int row = f >> 4, c4 = (f & 15) * 4;
      xr[i] = *(const float4*)(x + (size_t)(rowBase + row) * CC + k0 + c4);
    }
  };
  auto convertX = [&](int st) {
    const uint32_t xh = xhiB(st), xl = xloB(st);
    #pragma unroll
    for (int i = 0; i < 4; i++) {
      int f = i * 256 + tid;
      int row = f >> 4;
      uint32_t boff = (uint32_t)(row * PPITCH + (f & 15) * 8);
      float4 v = xr[i];
      uint32_t h01, h23, l01, l23;
      f16split2(v.x, v.y, h01, l01);
      f16split2(v.z, v.w, h23, l23);
      asm volatile("st.shared.v2.b32 [%0], {%1,%2};" :: "r"(xh + boff), "r"(h01), "r"(h23) : "memory");
      asm volatile("st.shared.v2.b32 [%0], {%1,%2};" :: "r"(xl + boff), "r"(l01), "r"(l23) : "memory");
    }
  };
  // W chunk: 192 rows x 64 fp16 = 8 x 16B per row = 1536 cp.async -> 6/thread
  auto issueW = [&](int chunk, int st) {
    const int k0 = chunk * KC;
    const uint32_t wb = wB(st);
    #pragma unroll
    for (int i = 0; i < 6; i++) {
      int gid = i * 256 + tid;             // 0..1535
      int n = gid >> 3, c = gid & 7;
      cpasync16u(wb + (uint32_t)(n * PPITCH + c * 16),
                 g_wth + (size_t)n * CC + k0 + c * 8);
    }
    cp_commit();
  };

  loadX(0);
  issueW(0, 0);
  convertX(0);
  loadX(1);

  for (int it = 0; it < NCHUNK; it++) {
    const int cur = it & 1;
    cp_wait0();
    __syncthreads();
    if (it + 1 < NCHUNK) issueW(it + 1, cur ^ 1);

    #pragma unroll
    for (int ks = 0; ks < 4; ks++) {
      uint32_t ah[4], al[4];
      ldm4(ah, xhiB(cur) + aOff + (uint32_t)(ks * 32));
      ldm4(al, xloB(cur) + aOff + (uint32_t)(ks * 32));
      #pragma unroll
      for (int nf2 = 0; nf2 < 6; nf2++) {
        uint32_t bw[4];
        ldm4(bw, wB(cur) + bOff + (uint32_t)(nf2 * 16 * PPITCH + ks * 32));
        #pragma unroll
        for (int s = 0; s < 2; s++) {
          float* dd = d[2 * nf2 + s];
          mma16816h(dd, ah, bw[2 * s], bw[2 * s + 1]);
          mma16816h(dd, al, bw[2 * s], bw[2 * s + 1]);
        }
      }
    }

    if (it + 1 < NCHUNK) convertX(cur ^ 1);
    if (it + 2 < NCHUNK) loadX(it + 2);
  }

  // epilogue: Q single (x0.125), K single, V split
  const int erow = lane >> 2;
  const int ecol = (lane & 3) * 2;
  #pragma unroll
  for (int nf = 0; nf < 12; nf++) {
    int n0 = wn + nf * 8;
    int part = n0 >> 6;
    int col = (n0 & 63) + ecol;
    size_t r0 = (size_t)(rowBase + wm + erow);
    size_t r1 = r0 + 8;
    if (part == 0) {        // K
      *(uint32_t*)(g_kh + r0 * DD + col) = f16pack2(d[nf][0], d[nf][1]);
      *(uint32_t*)(g_kh + r1 * DD + col) = f16pack2(d[nf][2], d[nf][3]);
    } else if (part == 1) { // Q, pre-scaled
      *(uint32_t*)(g_qh + r0 * DD + col) = f16pack2(d[nf][0] * 0.125f, d[nf][1] * 0.125f);
      *(uint32_t*)(g_qh + r1 * DD + col) = f16pack2(d[nf][2] * 0.125f, d[nf][3] * 0.125f);
    } else {                // V split hi/lo
      uint32_t h, l2;
      f16split2(d[nf][0], d[nf][1], h, l2);
      *(uint32_t*)(g_vh + r0 * DD + col) = h;
      *(uint32_t*)(g_vl + r0 * DD + col) = l2;
      f16split2(d[nf][2], d[nf][3], h, l2);
      *(uint32_t*)(g_vh + r1 * DD + col) = h;
      *(uint32_t*)(g_vl + r1 * DD + col) = l2;
    }
  }
}

// ---------------------------------------------------------------------------
// Kernel 2: FlashAttention-2 on fp16 mma.sync. 256 thr, 8 warps (m16 each),
// 128-query blocks, heavy-first. QK 1-term (Q,K single fp16), PV 2-term
// (P single, V hi/lo). Strided split-KV, double-buffered cp.async.
// ---------------------------------------------------------------------------
__global__ __launch_bounds__(256, 2) void attn_mma()
{
  const int qb  = (TT / 128 - 1) - blockIdx.x;   // heavy-first
  const int b   = blockIdx.y;
  const int sp  = blockIdx.z;
  const int tid = threadIdx.x;
  const int wid = tid >> 5;
  const int lane = tid & 31;

  const int ntt = 2 * (qb + 1);        // total 64-key tiles for this q-block
  const int nt  = (ntt > sp) ? (ntt - sp + 3) / 4 : 0;

  float o[8][4];
  #pragma unroll
  for (int nf = 0; nf < 8; nf++)
    #pragma unroll
    for (int c = 0; c < 4; c++) o[nf][c] = 0.f;
  float m0 = NEG_BIG, m1 = NEG_BIG, l0 = 0.f, l1 = 0.f;

  const int erow = lane >> 2;
  const int ecol = (lane & 3) * 2;
  const int row0g = b * TT + qb * 128 + wid * 16 + erow;

  if (nt == 0) goto epilogue;

  {
    const uint32_t sb  = smem_u32(dsmem);
    const uint32_t QS  = sb;
    const uint32_t KVB = sb + Q_BYTES;

    // ---- stage Q (group 0): 128 rows x 8 chunks = 1024 cp.async ----
    {
      const int rbase = b * TT + qb * 128;
      #pragma unroll
      for (int i = 0; i < 4; i++) {
        int gid = i * 256 + tid;               // 0..1023
        int row = gid >> 3, ch = gid & 7;
        cpasync16u(QS + (uint32_t)(row * APITCH + ch * 16),
                   g_qh + (size_t)(rbase + row) * DD + ch * 8);
      }
      cp_commit();
    }

    auto issueKV = [&](int j, int st) {
      const int k0 = j * 64;
      const uint32_t base = KVB + (uint32_t)st * KV_STAGE;
      #pragma unroll
      for (int i = 0; i < 6; i++) {
        int gid = i * 256 + tid;               // 0..1535
        int arr = gid >> 9;                    // 0=K,1=Vhi,2=Vlo
        int g2 = gid & 511;
        int row = g2 >> 3, ch = g2 & 7;
        const __half* ap = (arr == 0) ? g_kh : (arr == 1) ? g_vh : g_vl;
        cpasync16u(base + (uint32_t)(arr * KV_ARR + row * APITCH + ch * 16),
                   ap + (size_t)(b * TT + k0 + row) * DD + ch * 8);
      }
      cp_commit();
    };

    issueKV(sp, 0);          // group 1
    cp_wait1();              // Q (group 0) done
    __syncthreads();

    // ---- Q fragments (register-resident, single) ----
    const uint32_t qoff = (uint32_t)((wid * 16 + (lane & 15)) * APITCH + (lane >> 4) * 16);
    uint32_t qh[4][4];
    #pragma unroll
    for (int ks = 0; ks < 4; ks++) ldm4(qh[ks], QS + qoff + ks * 32);

    const uint32_t koff = (uint32_t)((((lane >> 4) & 1) * 8 + (lane & 7)) * APITCH + ((lane >> 3) & 1) * 16);
    const uint32_t voff = (uint32_t)((((lane >> 3) & 1) * 8 + (lane & 7)) * APITCH + ((lane >> 4) & 1) * 16);

    for (int tix = 0; tix < nt; tix++) {
      const int j  = sp + tix * 4;
      const int st = tix & 1;
      const int k0 = j * 64;
      cp_wait0();
      __syncthreads();
      if (tix + 1 < nt) issueKV(sp + (tix + 1) * 4, st ^ 1);

      const uint32_t stage = KVB + (uint32_t)st * KV_STAGE;
      const uint32_t KH = stage;
      const uint32_t VH = stage + KV_ARR, VL = stage + 2 * KV_ARR;

      // ---- S = Q K^T (1 term) ----
      float s[8][4];
      #pragma unroll
      for (int nf = 0; nf < 8; nf++)
        #pragma unroll
        for (int c = 0; c < 4; c++) s[nf][c] = 0.f;

      #pragma unroll
      for (int ks = 0; ks < 4; ks++) {
        #pragma unroll
        for (int g = 0; g < 4; g++) {
          uint32_t bh[4];
          ldm4(bh, KH + koff + (uint32_t)(g * 16 * APITCH + ks * 32));
          mma16816h(s[2*g],   qh[ks], bh[0], bh[1]);
          mma16816h(s[2*g+1], qh[ks], bh[2], bh[3]);
        }
      }

      // ---- causal mask (diagonal tiles only) ----
      if (k0 + 63 > qb * 128) {
        const int rlo = qb * 128 + wid * 16 + erow;
        #pragma unroll
        for (int nf = 0; nf < 8; nf++) {
          int key = k0 + nf * 8 + ecol;
          if (key     > rlo)     s[nf][0] = MASK_S;
          if (key + 1 > rlo)     s[nf][1] = MASK_S;
          if (key     > rlo + 8) s[nf][2] = MASK_S;
          if (key + 1 > rlo + 8) s[nf][3] = MASK_S;
        }
      }

      // ---- online softmax (fragment rows: l/4 and l/4+8) ----
      float r0 = fmaxf(s[0][0], s[0][1]);
      float r1 = fmaxf(s[0][2], s[0][3]);
      #pragma unroll
      for (int nf = 1; nf < 8; nf++) {
        r0 = fmaxf(r0, fmaxf(s[nf][0], s[nf][1]));
        r1 = fmaxf(r1, fmaxf(s[nf][2], s[nf][3]));
      }
      r0 = fmaxf(r0, __shfl_xor_sync(0xffffffffu, r0, 1));
      r0 = fmaxf(r0, __shfl_xor_sync(0xffffffffu, r0, 2));
      r1 = fmaxf(r1, __shfl_xor_sync(0xffffffffu, r1, 1));
      r1 = fmaxf(r1, __shfl_xor_sync(0xffffffffu, r1, 2));
      float mn0 = fmaxf(m0, r0), mn1 = fmaxf(m1, r1);
      float cr0 = __expf(m0 - mn0), cr1 = __expf(m1 - mn1);
      l0 *= cr0; l1 *= cr1; m0 = mn0; m1 = mn1;
      #pragma unroll
      for (int nf = 0; nf < 8; nf++) {
        o[nf][0] *= cr0; o[nf][1] *= cr0;
        o[nf][2] *= cr1; o[nf][3] *= cr1;
      }

      // ---- exp, row sums, P -> A-frag fp16 single ----
      float sum0 = 0.f, sum1 = 0.f;
      uint32_t ph[4][4];
      #pragma unroll
      for (int nf = 0; nf < 8; nf++) {
        float p0 = __expf(s[nf][0] - m0);
        float p1 = __expf(s[nf][1] - m0);
        float p2 = __expf(s[nf][2] - m1);
        float p3 = __expf(s[nf][3] - m1);
        sum0 += p0 + p1; sum1 += p2 + p3;
        int kk = nf >> 1, bs = (nf & 1) * 2;
        ph[kk][bs]     = f16pack2(p0, p1);
        ph[kk][bs + 1] = f16pack2(p2, p3);
      }
      sum0 += __shfl_xor_sync(0xffffffffu, sum0, 1);
      sum0 += __shfl_xor_sync(0xffffffffu, sum0, 2);
      sum1 += __shfl_xor_sync(0xffffffffu, sum1, 1);
      sum1 += __shfl_xor_sync(0xffffffffu, sum1, 2);
      l0 += sum0; l1 += sum1;

      // ---- O += P V (2 terms: P single, V hi/lo; V via trans-ldmatrix) ----
      #pragma unroll
      for (int kk = 0; kk < 4; kk++) {
        #pragma unroll
        for (int dg = 0; dg < 4; dg++) {
          uint32_t vh[4], vl[4];
          uint32_t off = voff + (uint32_t)(kk * 16 * APITCH + dg * 32);
          ldm4t(vh, VH + off);
          ldm4t(vl, VL + off);
          mma16816h(o[2*dg],   ph[kk], vh[0], vh[1]);
          mma16816h(o[2*dg+1], ph[kk], vh[2], vh[3]);
          mma16816h(o[2*dg],   ph[kk], vl[0], vl[1]);
          mma16816h(o[2*dg+1], ph[kk], vl[2], vl[3]);
        }
      }
    }
  }

epilogue:
  {
    size_t pr0 = (size_t)sp * ROWS + row0g;
    size_t pr1 = pr0 + 8;
    if ((lane & 3) == 0) {
      g_pm[pr0] = m0; g_pl[pr0] = l0;
      g_pm[pr1] = m1; g_pl[pr1] = l1;
    }
    #pragma unroll
    for (int nf = 0; nf < 8; nf++) {
      int col = nf * 8 + ecol;
      *(float2*)(g_po + pr0 * DD + col) = make_float2(o[nf][0], o[nf][1]);
      *(float2*)(g_po + pr1 * DD + col) = make_float2(o[nf][2], o[nf][3]);
    }
  }
}

// ---------------------------------------------------------------------------
// Kernel 3: LSE combine. One thread per output float4. grid=1024.
// ---------------------------------------------------------------------------
__global__ __launch_bounds__(256) void combine_kernel(float* __restrict__ out)
{
  int gid = blockIdx.x * 256 + threadIdx.x;   // 0 .. ROWS*16-1
  int r  = gid >> 4;
  int c  = (gid & 15) * 4;

  float m[S_SPLIT], l[S_SPLIT];
  #pragma unroll
  for (int s = 0; s < S_SPLIT; s++) {
    m[s] = g_pm[(size_t)s * ROWS + r];
    l[s] = g_pl[(size_t)s * ROWS + r];
  }
  float M = fmaxf(fmaxf(m[0], m[1]), fmaxf(m[2], m[3]));
  float w[S_SPLIT]; float L = 0.f;
  #pragma unroll
  for (int s = 0; s < S_SPLIT; s++) { w[s] = __expf(m[s] - M); L += l[s] * w[s]; }
  float inv = 1.0f / L;

  float4 acc = make_float4(0.f, 0.f, 0.f, 0.f);
  #pragma unroll
  for (int s = 0; s < S_SPLIT; s++) {
    float4 p = *(const float4*)(g_po + ((size_t)s * ROWS + r) * DD + c);
    acc.x += p.x * w[s]; acc.y += p.y * w[s];
    acc.z += p.z * w[s]; acc.w += p.w * w[s];
  }
  acc.x *= inv; acc.y *= inv; acc.z *= inv; acc.w *= inv;
  *(float4*)(out + (size_t)r * DD + c) = acc;
}

// ---------------------------------------------------------------------------
extern "C" void kernel_launch(void* const* d_in, const int* in_sizes, int n_in,
                              void* d_out, int out_size)
{
  const float* x  = (const float*)d_in[0];
  const float* Wk = (const float*)d_in[1];
  const float* Wq = (const float*)d_in[2];
  const float* Wv = (const float*)d_in[3];
  float* out = (float*)d_out;

  cudaFuncSetAttribute(proj_mma, cudaFuncAttributeMaxDynamicSharedMemorySize, SMEM_PROJ);
  cudaFuncSetAttribute(attn_mma, cudaFuncAttributeMaxDynamicSharedMemorySize, SMEM_ATT);

  prep_w<<<NTOT, 256>>>(Wk, Wq, Wv);
  proj_mma<<<ROWS / PM, 256, SMEM_PROJ>>>(x);
  attn_mma<<<dim3(TT / 128, BB, S_SPLIT), 256, SMEM_ATT>>>();
  combine_kernel<<<ROWS * 16 / 256, 256>>>(out);
}

// round 12
// speedup vs baseline: 2.7929x; 1.1154x over previous
#include <cuda_runtime.h>
#include <cuda_fp16.h>
#include <cstdint>

// Problem dims (fixed by reference)
#define BB 8
#define TT 2048
#define CC 1024
#define DD 64
#define ROWS (BB*TT)      // 16384
#define S_SPLIT 4
#define NEG_BIG  (-1.0e30f)
#define MASK_S   (-3.0e38f)

#define NTOT 192          // fused proj cols: 64 K | 64 Q | 64 V
#define KC 64             // K-chunk per pipeline stage (fp16 elems)
#define NCHUNK (CC/KC)    // 16

// proj smem: rows of 64 fp16 = 128B + 16B pad -> 144B pitch
#define PPITCH 144
#define PM 64                             // rows per proj CTA
#define XH_BYTES (PM*PPITCH)              // 9216
#define WH_BYTES (NTOT*PPITCH)            // 27648
#define STAGE_BYTES (XH_BYTES + WH_BYTES)     // 36864 (x single, w single)
#define SMEM_PROJ (2*STAGE_BYTES)             // 73728 -> 2+ CTAs/SM

// attn smem
#define APITCH 144
#define Q_BYTES (128*APITCH)        // 18432 (Q single fp16)
#define KV_ARR  (64*APITCH)         // 9216
#define KV_STAGE (3*KV_ARR)         // 27648 (K, Vhi, Vlo)
#define SMEM_ATT (Q_BYTES + 2*KV_STAGE)   // 73728 -> 2 CTAs/SM

// Scratch (allocation-free: __device__ globals)
__device__ float g_po[S_SPLIT*ROWS*DD];
__device__ float g_pm[S_SPLIT*ROWS];
__device__ float g_pl[S_SPLIT*ROWS];
__device__ __half g_wth[NTOT*CC];           // W^T fp16 single, [n][k]
__device__ __half g_qh[ROWS*DD];            // Q fp16 (pre-scaled 0.125)
__device__ __half g_kh[ROWS*DD];            // K fp16
__device__ __half g_vh[ROWS*DD], g_vl[ROWS*DD];   // V fp16 hi/lo

__device__ __forceinline__ void cpasync16u(uint32_t sa, const void* g){
  asm volatile("cp.async.cg.shared.global [%0], [%1], 16;\n" :: "r"(sa), "l"(g) : "memory");
}
__device__ __forceinline__ void cp_commit(){ asm volatile("cp.async.commit_group;\n" ::: "memory"); }
__device__ __forceinline__ void cp_wait0(){ asm volatile("cp.async.wait_group 0;\n" ::: "memory"); }
__device__ __forceinline__ void cp_wait1(){ asm volatile("cp.async.wait_group 1;\n" ::: "memory"); }

__device__ __forceinline__ uint32_t smem_u32(const void* p){
  return (uint32_t)__cvta_generic_to_shared(p);
}
__device__ __forceinline__ void ldm4(uint32_t* r, uint32_t addr){
  asm volatile("ldmatrix.sync.aligned.m8n8.x4.shared.b16 {%0,%1,%2,%3},[%4];"
    : "=r"(r[0]), "=r"(r[1]), "=r"(r[2]), "=r"(r[3]) : "r"(addr));
}
__device__ __forceinline__ void ldm4t(uint32_t* r, uint32_t addr){
  asm volatile("ldmatrix.sync.aligned.m8n8.x4.trans.shared.b16 {%0,%1,%2,%3},[%4];"
    : "=r"(r[0]), "=r"(r[1]), "=r"(r[2]), "=r"(r[3]) : "r"(addr));
}
// fp16 mma: m16n8k16, f32 accum
__device__ __forceinline__ void mma16816h(float* d, const uint32_t* a,
                                          uint32_t b0, uint32_t b1){
  asm volatile("mma.sync.aligned.m16n8k16.row.col.f32.f16.f16.f32 "
    "{%0,%1,%2,%3},{%4,%5,%6,%7},{%8,%9},{%0,%1,%2,%3};"
    : "+f"(d[0]), "+f"(d[1]), "+f"(d[2]), "+f"(d[3])
    : "r"(a[0]), "r"(a[1]), "r"(a[2]), "r"(a[3]), "r"(b0), "r"(b1));
}
// pack (a -> low half, b -> high half) as f16x2
__device__ __forceinline__ uint32_t f16pack2(float a, float b){
  uint32_t r; asm("cvt.rn.f16x2.f32 %0, %1, %2;" : "=r"(r) : "f"(b), "f"(a));
  return r;
}
// fp16 split with exact fp32 residual in lo
__device__ __forceinline__ void f16split2(float a, float b, uint32_t &hi, uint32_t &lo){
  asm("cvt.rn.f16x2.f32 %0, %1, %2;" : "=r"(hi) : "f"(b), "f"(a));
  float fa, fb;
  asm("{ .reg .f16 l_, h_;\n\t mov.b32 {l_, h_}, %2;\n\t"
      "cvt.f32.f16 %0, l_;\n\t cvt.f32.f16 %1, h_;\n\t }"
      : "=f"(fa), "=f"(fb) : "r"(hi));
  asm("cvt.rn.f16x2.f32 %0, %1, %2;" : "=r"(lo) : "f"(b - fb), "f"(a - fa));
}

// ---------------------------------------------------------------------------
// Kernel 0: W -> fp16 single, transposed [n][k].
// ---------------------------------------------------------------------------
__global__ __launch_bounds__(256) void prep_w(
    const float* __restrict__ Wk, const float* __restrict__ Wq,
    const float* __restrict__ Wv)
{
  int n = blockIdx.x;
  const float* W = (n < 64) ? Wk : ((n < 128) ? Wq : Wv);
  int col = n & 63;
  for (int k = threadIdx.x; k < CC; k += 256)
    g_wth[n * CC + k] = __float2half(W[(size_t)k * DD + col]);
}

// ---------------------------------------------------------------------------
// Kernel 1: QKV projection, fp16 1-term (x single, W single).
// grid = 256 CTAs x 64 rows, 256 thr (8 warps), warp tile 16x96,
// KC=64 (4 k16 steps), double-buffered. Epilogue: Q single fp16 (x0.125),
// K single fp16, V fp16 hi/lo split.
// ---------------------------------------------------------------------------
extern __shared__ char dsmem[];

__global__ __launch_bounds__(256, 2) void proj_mma(const float* __restrict__ x)
{
  const int tid  = threadIdx.x;
  const int wid  = tid >> 5;
  const int lane = tid & 31;
  const int rowBase = blockIdx.x * PM;

  const uint32_t sbase = smem_u32(dsmem);
  auto xB = [&](int st){ return sbase + (uint32_t)st * STAGE_BYTES; };
  auto wB = [&](int st){ return xB(st) + XH_BYTES; };

  const int wm = (wid & 3) * 16;       // 4 row groups x 16
  const int wn = (wid >> 2) * 96;      // 2 col groups x 96

  const uint32_t aOff = (uint32_t)((wm + (lane & 15)) * PPITCH + (lane >> 4) * 16);
  const int bN = wn + ((lane >> 4) & 1) * 8 + (lane & 7);
  const uint32_t bOff = (uint32_t)(bN * PPITCH + ((lane >> 3) & 1) * 16);

  float d[12][4];
  #pragma unroll
  for (int nf = 0; nf < 12; nf++)
    #pragma unroll
    for (int c = 0; c < 4; c++) d[nf][c] = 0.f;

  // x chunk: 64 rows x 64 cols fp32 = 1024 float4 -> 4/thread
  float4 xr[4];
  auto loadX = [&](int chunk) {
    const int k0 = chunk * KC;
    #pragma unroll
    for (int i = 0; i < 4; i++) {
      int f = i * 256 + tid;            // 0..1023
      int row = f >> 4, c4 = (f & 15) * 4;
      xr[i] = *(const float4*)(x + (size_t)(rowBase + row) * CC + k0 + c4);
    }
  };
  auto convertX = [&](int st) {
    const uint32_t xh = xB(st);
    #pragma unroll
    for (int i = 0; i < 4; i++) {
      int f = i * 256 + tid;
      int row = f >> 4;
      uint32_t boff = (uint32_t)(row * PPITCH + (f & 15) * 8);
      float4 v = xr[i];
      uint32_t h01 = f16pack2(v.x, v.y);
      uint32_t h23 = f16pack2(v.z, v.w);
      asm volatile("st.shared.v2.b32 [%0], {%1,%2};" :: "r"(xh + boff), "r"(h01), "r"(h23) : "memory");
    }
  };
  // W chunk: 192 rows x 64 fp16 = 8 x 16B per row = 1536 cp.async -> 6/thread
  auto issueW = [&](int chunk, int st) {
    const int k0 = chunk * KC;
    const uint32_t wb = wB(st);
    #pragma unroll
    for (int i = 0; i < 6; i++) {
      int gid = i * 256 + tid;             // 0..1535
      int n = gid >> 3, c = gid & 7;
      cpasync16u(wb + (uint32_t)(n * PPITCH + c * 16),
                 g_wth + (size_t)n * CC + k0 + c * 8);
    }
    cp_commit();
  };

  loadX(0);
  issueW(0, 0);
  convertX(0);
  loadX(1);

  for (int it = 0; it < NCHUNK; it++) {
    const int cur = it & 1;
    cp_wait0();
    __syncthreads();
    if (it + 1 < NCHUNK) issueW(it + 1, cur ^ 1);

    #pragma unroll
    for (int ks = 0; ks < 4; ks++) {
      uint32_t ah[4];
      ldm4(ah, xB(cur) + aOff + (uint32_t)(ks * 32));
      #pragma unroll
      for (int nf2 = 0; nf2 < 6; nf2++) {
        uint32_t bw[4];
        ldm4(bw, wB(cur) + bOff + (uint32_t)(nf2 * 16 * PPITCH + ks * 32));
        mma16816h(d[2 * nf2],     ah, bw[0], bw[1]);
        mma16816h(d[2 * nf2 + 1], ah, bw[2], bw[3]);
      }
    }

    if (it + 1 < NCHUNK) convertX(cur ^ 1);
    if (it + 2 < NCHUNK) loadX(it + 2);
  }

  // epilogue: Q single (x0.125), K single, V split hi/lo
  const int erow = lane >> 2;
  const int ecol = (lane & 3) * 2;
  #pragma unroll
  for (int nf = 0; nf < 12; nf++) {
    int n0 = wn + nf * 8;
    int part = n0 >> 6;
    int col = (n0 & 63) + ecol;
    size_t r0 = (size_t)(rowBase + wm + erow);
    size_t r1 = r0 + 8;
    if (part == 0) {        // K
      *(uint32_t*)(g_kh + r0 * DD + col) = f16pack2(d[nf][0], d[nf][1]);
      *(uint32_t*)(g_kh + r1 * DD + col) = f16pack2(d[nf][2], d[nf][3]);
    } else if (part == 1) { // Q, pre-scaled
      *(uint32_t*)(g_qh + r0 * DD + col) = f16pack2(d[nf][0] * 0.125f, d[nf][1] * 0.125f);
      *(uint32_t*)(g_qh + r1 * DD + col) = f16pack2(d[nf][2] * 0.125f, d[nf][3] * 0.125f);
    } else {                // V split hi/lo
      uint32_t h, l2;
      f16split2(d[nf][0], d[nf][1], h, l2);
      *(uint32_t*)(g_vh + r0 * DD + col) = h;
      *(uint32_t*)(g_vl + r0 * DD + col) = l2;
      f16split2(d[nf][2], d[nf][3], h, l2);
      *(uint32_t*)(g_vh + r1 * DD + col) = h;
      *(uint32_t*)(g_vl + r1 * DD + col) = l2;
    }
  }
}

// ---------------------------------------------------------------------------
// Kernel 2: FlashAttention-2 on fp16 mma.sync. 256 thr, 8 warps (m16 each),
// 128-query blocks, heavy-first. QK 1-term (Q,K single fp16), PV 2-term
// (P single, V hi/lo). Strided split-KV, double-buffered cp.async.
// ---------------------------------------------------------------------------
__global__ __launch_bounds__(256, 2) void attn_mma()
{
  const int qb  = (TT / 128 - 1) - blockIdx.x;   // heavy-first
  const int b   = blockIdx.y;
  const int sp  = blockIdx.z;
  const int tid = threadIdx.x;
  const int wid = tid >> 5;
  const int lane = tid & 31;

  const int ntt = 2 * (qb + 1);        // total 64-key tiles for this q-block
  const int nt  = (ntt > sp) ? (ntt - sp + 3) / 4 : 0;

  float o[8][4];
  #pragma unroll
  for (int nf = 0; nf < 8; nf++)
    #pragma unroll
    for (int c = 0; c < 4; c++) o[nf][c] = 0.f;
  float m0 = NEG_BIG, m1 = NEG_BIG, l0 = 0.f, l1 = 0.f;

  const int erow = lane >> 2;
  const int ecol = (lane & 3) * 2;
  const int row0g = b * TT + qb * 128 + wid * 16 + erow;

  if (nt == 0) goto epilogue;

  {
    const uint32_t sb  = smem_u32(dsmem);
    const uint32_t QS  = sb;
    const uint32_t KVB = sb + Q_BYTES;

    // ---- stage Q (group 0): 128 rows x 8 chunks = 1024 cp.async ----
    {
      const int rbase = b * TT + qb * 128;
      #pragma unroll
      for (int i = 0; i < 4; i++) {
        int gid = i * 256 + tid;               // 0..1023
        int row = gid >> 3, ch = gid & 7;
        cpasync16u(QS + (uint32_t)(row * APITCH + ch * 16),
                   g_qh + (size_t)(rbase + row) * DD + ch * 8);
      }
      cp_commit();
    }

    auto issueKV = [&](int j, int st) {
      const int k0 = j * 64;
      const uint32_t base = KVB + (uint32_t)st * KV_STAGE;
      #pragma unroll
      for (int i = 0; i < 6; i++) {
        int gid = i * 256 + tid;               // 0..1535
        int arr = gid >> 9;                    // 0=K,1=Vhi,2=Vlo
        int g2 = gid & 511;
        int row = g2 >> 3, ch = g2 & 7;
        const __half* ap = (arr == 0) ? g_kh : (arr == 1) ? g_vh : g_vl;
        cpasync16u(base + (uint32_t)(arr * KV_ARR + row * APITCH + ch * 16),
                   ap + (size_t)(b * TT + k0 + row) * DD + ch * 8);
      }
      cp_commit();
    };

    issueKV(sp, 0);          // group 1
    cp_wait1();              // Q (group 0) done
    __syncthreads();

    // ---- Q fragments (register-resident, single) ----
    const uint32_t qoff = (uint32_t)((wid * 16 + (lane & 15)) * APITCH + (lane >> 4) * 16);
    uint32_t qh[4][4];
    #pragma unroll
    for (int ks = 0; ks < 4; ks++) ldm4(qh[ks], QS + qoff + ks * 32);

    const uint32_t koff = (uint32_t)((((lane >> 4) & 1) * 8 + (lane & 7)) * APITCH + ((lane >> 3) & 1) * 16);
    const uint32_t voff = (uint32_t)((((lane >> 3) & 1) * 8 + (lane & 7)) * APITCH + ((lane >> 4) & 1) * 16);

    for (int tix = 0; tix < nt; tix++) {
      const int j  = sp + tix * 4;
      const int st = tix & 1;
      const int k0 = j * 64;
      cp_wait0();
      __syncthreads();
      if (tix + 1 < nt) issueKV(sp + (tix + 1) * 4, st ^ 1);

      const uint32_t stage = KVB + (uint32_t)st * KV_STAGE;
      const uint32_t KH = stage;
      const uint32_t VH = stage + KV_ARR, VL = stage + 2 * KV_ARR;

      // ---- S = Q K^T (1 term) ----
      float s[8][4];
      #pragma unroll
      for (int nf = 0; nf < 8; nf++)
        #pragma unroll
        for (int c = 0; c < 4; c++) s[nf][c] = 0.f;

      #pragma unroll
      for (int ks = 0; ks < 4; ks++) {
        #pragma unroll
        for (int g = 0; g < 4; g++) {
          uint32_t bh[4];
          ldm4(bh, KH + koff + (uint32_t)(g * 16 * APITCH + ks * 32));
          mma16816h(s[2*g],   qh[ks], bh[0], bh[1]);
          mma16816h(s[2*g+1], qh[ks], bh[2], bh[3]);
        }
      }

      // ---- causal mask (diagonal tiles only) ----
      if (k0 + 63 > qb * 128) {
        const int rlo = qb * 128 + wid * 16 + erow;
        #pragma unroll
        for (int nf = 0; nf < 8; nf++) {
          int key = k0 + nf * 8 + ecol;
          if (key     > rlo)     s[nf][0] = MASK_S;
          if (key + 1 > rlo)     s[nf][1] = MASK_S;
          if (key     > rlo + 8) s[nf][2] = MASK_S;
          if (key + 1 > rlo + 8) s[nf][3] = MASK_S;
        }
      }

      // ---- online softmax (fragment rows: l/4 and l/4+8) ----
      float r0 = fmaxf(s[0][0], s[0][1]);
      float r1 = fmaxf(s[0][2], s[0][3]);
      #pragma unroll
      for (int nf = 1; nf < 8; nf++) {
        r0 = fmaxf(r0, fmaxf(s[nf][0], s[nf][1]));
        r1 = fmaxf(r1, fmaxf(s[nf][2], s[nf][3]));
      }
      r0 = fmaxf(r0, __shfl_xor_sync(0xffffffffu, r0, 1));
      r0 = fmaxf(r0, __shfl_xor_sync(0xffffffffu, r0, 2));
      r1 = fmaxf(r1, __shfl_xor_sync(0xffffffffu, r1, 1));
      r1 = fmaxf(r1, __shfl_xor_sync(0xffffffffu, r1, 2));
      float mn0 = fmaxf(m0, r0), mn1 = fmaxf(m1, r1);
      float cr0 = __expf(m0 - mn0), cr1 = __expf(m1 - mn1);
      l0 *= cr0; l1 *= cr1; m0 = mn0; m1 = mn1;
      #pragma unroll
      for (int nf = 0; nf < 8; nf++) {
        o[nf][0] *= cr0; o[nf][1] *= cr0;
        o[nf][2] *= cr1; o[nf][3] *= cr1;
      }

      // ---- exp, row sums, P -> A-frag fp16 single ----
      float sum0 = 0.f, sum1 = 0.f;
      uint32_t ph[4][4];
      #pragma unroll
      for (int nf = 0; nf < 8; nf++) {
        float p0 = __expf(s[nf][0] - m0);
        float p1 = __expf(s[nf][1] - m0);
        float p2 = __expf(s[nf][2] - m1);
        float p3 = __expf(s[nf][3] - m1);
        sum0 += p0 + p1; sum1 += p2 + p3;
        int kk = nf >> 1, bs = (nf & 1) * 2;
        ph[kk][bs]     = f16pack2(p0, p1);
        ph[kk][bs + 1] = f16pack2(p2, p3);
      }
      sum0 += __shfl_xor_sync(0xffffffffu, sum0, 1);
      sum0 += __shfl_xor_sync(0xffffffffu, sum0, 2);
      sum1 += __shfl_xor_sync(0xffffffffu, sum1, 1);
      sum1 += __shfl_xor_sync(0xffffffffu, sum1, 2);
      l0 += sum0; l1 += sum1;

      // ---- O += P V (2 terms: P single, V hi/lo; V via trans-ldmatrix) ----
      #pragma unroll
      for (int kk = 0; kk < 4; kk++) {
        #pragma unroll
        for (int dg = 0; dg < 4; dg++) {
          uint32_t vh[4], vl[4];
          uint32_t off = voff + (uint32_t)(kk * 16 * APITCH + dg * 32);
          ldm4t(vh, VH + off);
          ldm4t(vl, VL + off);
          mma16816h(o[2*dg],   ph[kk], vh[0], vh[1]);
          mma16816h(o[2*dg+1], ph[kk], vh[2], vh[3]);
          mma16816h(o[2*dg],   ph[kk], vl[0], vl[1]);
          mma16816h(o[2*dg+1], ph[kk], vl[2], vl[3]);
        }
      }
    }
  }

epilogue:
  {
    size_t pr0 = (size_t)sp * ROWS + row0g;
    size_t pr1 = pr0 + 8;
    if ((lane & 3) == 0) {
      g_pm[pr0] = m0; g_pl[pr0] = l0;
      g_pm[pr1] = m1; g_pl[pr1] = l1;
    }
    #pragma unroll
    for (int nf = 0; nf < 8; nf++) {
      int col = nf * 8 + ecol;
      *(float2*)(g_po + pr0 * DD + col) = make_float2(o[nf][0], o[nf][1]);
      *(float2*)(g_po + pr1 * DD + col) = make_float2(o[nf][2], o[nf][3]);
    }
  }
}

// ---------------------------------------------------------------------------
// Kernel 3: LSE combine. One thread per output float4. grid=1024.
// ---------------------------------------------------------------------------
__global__ __launch_bounds__(256) void combine_kernel(float* __restrict__ out)
{
  int gid = blockIdx.x * 256 + threadIdx.x;   // 0 .. ROWS*16-1
  int r  = gid >> 4;
  int c  = (gid & 15) * 4;

  float m[S_SPLIT], l[S_SPLIT];
  #pragma unroll
  for (int s = 0; s < S_SPLIT; s++) {
    m[s] = g_pm[(size_t)s * ROWS + r];
    l[s] = g_pl[(size_t)s * ROWS + r];
  }
  float M = fmaxf(fmaxf(m[0], m[1]), fmaxf(m[2], m[3]));
  float w[S_SPLIT]; float L = 0.f;
  #pragma unroll
  for (int s = 0; s < S_SPLIT; s++) { w[s] = __expf(m[s] - M); L += l[s] * w[s]; }
  float inv = 1.0f / L;

  float4 acc = make_float4(0.f, 0.f, 0.f, 0.f);
  #pragma unroll
  for (int s = 0; s < S_SPLIT; s++) {
    float4 p = *(const float4*)(g_po + ((size_t)s * ROWS + r) * DD + c);
    acc.x += p.x * w[s]; acc.y += p.y * w[s];
    acc.z += p.z * w[s]; acc.w += p.w * w[s];
  }
  acc.x *= inv; acc.y *= inv; acc.z *= inv; acc.w *= inv;
  *(float4*)(out + (size_t)r * DD + c) = acc;
}

// ---------------------------------------------------------------------------
extern "C" void kernel_launch(void* const* d_in, const int* in_sizes, int n_in,
                              void* d_out, int out_size)
{
  const float* x  = (const float*)d_in[0];
  const float* Wk = (const float*)d_in[1];
  const float* Wq = (const float*)d_in[2];
  const float* Wv = (const float*)d_in[3];
  float* out = (float*)d_out;

  cudaFuncSetAttribute(proj_mma, cudaFuncAttributeMaxDynamicSharedMemorySize, SMEM_PROJ);
  cudaFuncSetAttribute(attn_mma, cudaFuncAttributeMaxDynamicSharedMemorySize, SMEM_ATT);

  prep_w<<<NTOT, 256>>>(Wk, Wq, Wv);
  proj_mma<<<ROWS / PM, 256, SMEM_PROJ>>>(x);
  attn_mma<<<dim3(TT / 128, BB, S_SPLIT), 256, SMEM_ATT>>>();
  combine_kernel<<<ROWS * 16 / 256, 256>>>(out);
}